// round 10
// baseline (speedup 1.0000x reference)
#include <cuda_runtime.h>
#include <cuda_fp16.h>
#include <cstddef>
#include <cstdint>

#define BATCH   64
#define NCAPS   32
#define NROUTES 2048
#define INDIM   16
#define OUTDIM  32
#define NITERS  3
#define NWARPS  16

// Global fp16 prior buffer (static device scratch — the sanctioned path).
// Layout (half2 units): pri[c][bp][n][b1][oh]  oh = o/2 (16 half2)
//   index = (((c*32 + bp)*2048 + n)*2 + b1)*16 + oh
__device__ __half2 g_pri[(size_t)NCAPS * 32 * NROUTES * 2 * 16];

// ================= K1: priors GEMM =================
// Grid 512 = (c, 128-route block). 512 thr: thread = (b = t>>3, og = t&7).
// Per 8-route chunk: stage x + W to SMEM, compute, write fp16 priors to global.
#define K1_XSH_STRIDE 132                   // floats per b (8 routes * 16 + 4 pad)
#define K1_XSH_FLOATS (64 * K1_XSH_STRIDE)  // 8448
#define K1_WSH_FLOATS (8 * 512)             // 4096
#define K1_SMEM_BYTES ((K1_XSH_FLOATS + K1_WSH_FLOATS) * 4)   // 50176

__global__ void __launch_bounds__(512, 4)
caps_k1_priors(const float* __restrict__ x, const float* __restrict__ W)
{
    extern __shared__ float k1sm[];
    float* xsh = k1sm;                    // [b][rl][i] stride 132 per b
    float* wsh = k1sm + K1_XSH_FLOATS;    // [rl][i][o] = [8][16][32]

    const int t  = threadIdx.x;
    const int b  = t >> 3;
    const int og = t & 7;
    const int c  = blockIdx.x >> 4;
    const int r0 = (blockIdx.x & 15) * 128;
    const int bp = b >> 1, b1 = b & 1;

    const float4* x4 = reinterpret_cast<const float4*>(x);
    const float4* W4 = reinterpret_cast<const float4*>(W);

    for (int chunk = 0; chunk < 16; chunk++) {
        const int rc = r0 + chunk * 8;

        // stage x: 2048 float4 (64 b x 8 r x 4 q)
#pragma unroll
        for (int k = 0; k < 4; k++) {
            int idx = t + k * 512;
            int bb = idx >> 5, rem = idx & 31;
            int rl = rem >> 2, q = rem & 3;
            float4 v = __ldg(x4 + ((size_t)bb * NROUTES + rc + rl) * 4 + q);
            *reinterpret_cast<float4*>(&xsh[bb * K1_XSH_STRIDE + rl * 16 + q * 4]) = v;
        }
        // stage W: 1024 float4 (8 r x 128)
#pragma unroll
        for (int k = 0; k < 2; k++) {
            int idx = t + k * 512;
            int rl = idx >> 7, rem = idx & 127;
            float4 v = __ldg(W4 + ((size_t)c * NROUTES + rc + rl) * 128 + rem);
            *reinterpret_cast<float4*>(&wsh[rl * 512 + rem * 4]) = v;
        }
        __syncthreads();

#pragma unroll
        for (int rl = 0; rl < 8; rl++) {
            float a0 = 0.f, a1 = 0.f, a2 = 0.f, a3 = 0.f;
#pragma unroll
            for (int q = 0; q < 4; q++) {
                float4 xq = *reinterpret_cast<const float4*>(
                    &xsh[b * K1_XSH_STRIDE + rl * 16 + q * 4]);
                const float* wb = &wsh[rl * 512 + q * 4 * 32 + og * 4];
                float4 w0 = *reinterpret_cast<const float4*>(wb);
                float4 w1 = *reinterpret_cast<const float4*>(wb + 32);
                float4 w2 = *reinterpret_cast<const float4*>(wb + 64);
                float4 w3 = *reinterpret_cast<const float4*>(wb + 96);
                a0 = fmaf(xq.x, w0.x, a0); a1 = fmaf(xq.x, w0.y, a1);
                a2 = fmaf(xq.x, w0.z, a2); a3 = fmaf(xq.x, w0.w, a3);
                a0 = fmaf(xq.y, w1.x, a0); a1 = fmaf(xq.y, w1.y, a1);
                a2 = fmaf(xq.y, w1.z, a2); a3 = fmaf(xq.y, w1.w, a3);
                a0 = fmaf(xq.z, w2.x, a0); a1 = fmaf(xq.z, w2.y, a1);
                a2 = fmaf(xq.z, w2.z, a2); a3 = fmaf(xq.z, w2.w, a3);
                a0 = fmaf(xq.w, w3.x, a0); a1 = fmaf(xq.w, w3.y, a1);
                a2 = fmaf(xq.w, w3.z, a2); a3 = fmaf(xq.w, w3.w, a3);
            }
            const int n = rc + rl;
            size_t off = ((((size_t)c * 32 + bp) * NROUTES + n) * 2 + b1) * 16 + og * 2;
            g_pri[off]     = __floats2half2_rn(a0, a1);
            g_pri[off + 1] = __floats2half2_rn(a2, a3);
        }
        __syncthreads();
    }
}

// ================= K2: routing =================
// Grid 1024 = (c, bp). Loads contiguous 256KB prior slice; R8 routing phase.
#define SPH 17
#define OFF_SP0   0
#define OFF_SP1   (1024 * SPH)
#define OFF_SCR   (2 * 1024 * SPH)            // in half2 units
#define N_SCRATCH (32 + 32 + 16 + NWARPS * 32 + 4)
#define K2_SMEM_BYTES ((OFF_SCR + N_SCRATCH) * 4)

__global__ void __launch_bounds__(512, 1)
caps_k2_route(float* __restrict__ out)
{
    extern __shared__ __half2 smh[];
    __half2* sp0 = smh + OFF_SP0;
    __half2* sp1 = smh + OFF_SP1;
    float* scr  = reinterpret_cast<float*>(smh + OFF_SCR);
    float* Vsh  = scr;                       // 32
    float* sred = scr + 32;                  // 32
    float* wred = scr + 64;                  // 16
    float* wvec = scr + 80;                  // 16*32
    float* scal = scr + 80 + NWARPS * 32;    // 4

    const int t    = threadIdx.x;
    const int lane = t & 31;
    const int wid  = t >> 5;
    const int c    = blockIdx.x >> 5;
    const int bp   = blockIdx.x & 31;

    const __half2* P = g_pri + (((size_t)c * 32 + bp) * NROUTES) * 32;  // 32 half2/route
    const float4*  P4 = reinterpret_cast<const float4*>(P);             // 8 float4/route

    // ---- pass 1: routes 1024..2047 -> sp rows 0..1023 ----
#pragma unroll 4
    for (int k = 0; k < 16; k++) {
        int idx = t + k * 512;
        int nl = idx >> 3, part = idx & 7;
        float4 v = __ldg(P4 + (size_t)(1024 + nl) * 8 + part);
        __half2* dst = ((part < 4) ? sp0 : sp1) + (size_t)nl * SPH + (part & 3) * 4;
        const __half2* h = reinterpret_cast<const __half2*>(&v);
        dst[0] = h[0]; dst[1] = h[1]; dst[2] = h[2]; dst[3] = h[3];
    }
    __syncthreads();

    // pull register rows: A = route 1024+t, B = route 1536+t (per batch)
    __half2 A0[16], B0[16], A1[16], B1[16];
    {
        const __half2* pA0 = sp0 + (size_t)t * SPH;
        const __half2* pB0 = sp0 + (size_t)(512 + t) * SPH;
        const __half2* pA1 = sp1 + (size_t)t * SPH;
        const __half2* pB1 = sp1 + (size_t)(512 + t) * SPH;
#pragma unroll
        for (int j = 0; j < 16; j++) {
            A0[j] = pA0[j]; B0[j] = pB0[j];
            A1[j] = pA1[j]; B1[j] = pB1[j];
        }
    }
    __syncthreads();

    // ---- pass 2: routes 0..1023 -> sp rows ----
#pragma unroll 4
    for (int k = 0; k < 16; k++) {
        int idx = t + k * 512;
        int nl = idx >> 3, part = idx & 7;
        float4 v = __ldg(P4 + (size_t)nl * 8 + part);
        __half2* dst = ((part < 4) ? sp0 : sp1) + (size_t)nl * SPH + (part & 3) * 4;
        const __half2* h = reinterpret_cast<const __half2*>(&v);
        dst[0] = h[0]; dst[1] = h[1]; dst[2] = h[2]; dst[3] = h[3];
    }
    __syncthreads();

    // ---- routing (R8 phase 2; A,B = reg routes 1024+t/1536+t; C,D = smem routes t/512+t) ----
    for (int bb = 0; bb < 2; bb++) {
        const __half2* A   = bb ? A1 : A0;
        const __half2* B   = bb ? B1 : B0;
        const __half2* spC = (bb ? sp1 : sp0) + (size_t)t * SPH;
        const __half2* spD = (bb ? sp1 : sp0) + (size_t)(512 + t) * SPH;
        const int bout = 2 * bp + bb;

        if (t < 32) Vsh[t] = 0.f;
        __syncthreads();

        for (int it = 0; it < NITERS; it++) {
            float p0, p1, p2, p3;
            if (it == 0) {
                p0 = p1 = p2 = p3 = 1.0f / (float)NROUTES;
            } else {
                float l0 = 0.f, l1 = 0.f, l2 = 0.f, l3 = 0.f;
#pragma unroll
                for (int j = 0; j < 16; j++) {
                    float v0 = Vsh[2 * j], v1 = Vsh[2 * j + 1];
                    float2 a = __half22float2(A[j]);
                    float2 b2 = __half22float2(B[j]);
                    float2 cc = __half22float2(spC[j]);
                    float2 dd = __half22float2(spD[j]);
                    l0 += a.x * v0 + a.y * v1;
                    l1 += b2.x * v0 + b2.y * v1;
                    l2 += cc.x * v0 + cc.y * v1;
                    l3 += dd.x * v0 + dd.y * v1;
                }
                float m = fmaxf(fmaxf(l0, l1), fmaxf(l2, l3));
#pragma unroll
                for (int s = 16; s; s >>= 1) m = fmaxf(m, __shfl_xor_sync(0xffffffffu, m, s));
                if (lane == 0) wred[wid] = m;
                __syncthreads();
                if (wid == 0) {
                    float mm = (lane < NWARPS) ? wred[lane] : -3.402823e38f;
#pragma unroll
                    for (int s = 16; s; s >>= 1) mm = fmaxf(mm, __shfl_xor_sync(0xffffffffu, mm, s));
                    if (lane == 0) scal[0] = mm;
                }
                __syncthreads();
                const float bmax = scal[0];

                float e0 = __expf(l0 - bmax);
                float e1 = __expf(l1 - bmax);
                float e2 = __expf(l2 - bmax);
                float e3 = __expf(l3 - bmax);
                float zs = e0 + e1 + e2 + e3;
#pragma unroll
                for (int s = 16; s; s >>= 1) zs += __shfl_xor_sync(0xffffffffu, zs, s);
                if (lane == 0) wred[wid] = zs;
                __syncthreads();
                if (wid == 0) {
                    float zz = (lane < NWARPS) ? wred[lane] : 0.f;
#pragma unroll
                    for (int s = 16; s; s >>= 1) zz += __shfl_xor_sync(0xffffffffu, zz, s);
                    if (lane == 0) scal[1] = zz;
                }
                __syncthreads();
                const float invZ = 1.0f / scal[1];
                p0 = e0 * invZ; p1 = e1 * invZ; p2 = e2 * invZ; p3 = e3 * invZ;
            }

            float ps[OUTDIM];
#pragma unroll
            for (int j = 0; j < 16; j++) {
                float2 a = __half22float2(A[j]);
                float2 b2 = __half22float2(B[j]);
                float2 cc = __half22float2(spC[j]);
                float2 dd = __half22float2(spD[j]);
                ps[2 * j]     = p0 * a.x + p1 * b2.x + p2 * cc.x + p3 * dd.x;
                ps[2 * j + 1] = p0 * a.y + p1 * b2.y + p2 * cc.y + p3 * dd.y;
            }
#pragma unroll
            for (int s = 16; s; s >>= 1) {
#pragma unroll
                for (int o = 0; o < OUTDIM; o++)
                    ps[o] += __shfl_xor_sync(0xffffffffu, ps[o], s);
            }
            if (lane == 0) {
#pragma unroll
                for (int o = 0; o < OUTDIM; o++) wvec[wid * 32 + o] = ps[o];
            }
            __syncthreads();
            if (t < 32) {
                float sv = 0.f;
#pragma unroll
                for (int w = 0; w < NWARPS; w++) sv += wvec[w * 32 + t];
                sred[t] = sv;
            }
            __syncthreads();

            if (t < 32) {
                float nr = 0.f;
#pragma unroll
                for (int o = 0; o < OUTDIM; o++) { float sv = sred[o]; nr += sv * sv; }
                float scale = (nr / (1.0f + nr)) * rsqrtf(nr);
                float v = scale * sred[t];
                Vsh[t] += v;
                if (it == NITERS - 1)
                    out[((size_t)bout * NCAPS + c) * OUTDIM + t] = v;
            }
            __syncthreads();
        }
    }
}

extern "C" void kernel_launch(void* const* d_in, const int* in_sizes, int n_in,
                              void* d_out, int out_size)
{
    const float* x = (const float*)d_in[0];         // [64, 2048, 16]
    const float* W = (const float*)d_in[1];         // [32, 2048, 16, 32]
    float* out = (float*)d_out;                     // [64, 32, 32]

    cudaFuncSetAttribute(caps_k1_priors,
                         cudaFuncAttributeMaxDynamicSharedMemorySize, K1_SMEM_BYTES);
    cudaFuncSetAttribute(caps_k2_route,
                         cudaFuncAttributeMaxDynamicSharedMemorySize, K2_SMEM_BYTES);

    caps_k1_priors<<<NCAPS * 16, 512, K1_SMEM_BYTES>>>(x, W);   // (c, route-block)
    caps_k2_route<<<NCAPS * 32, 512, K2_SMEM_BYTES>>>(out);     // (c, bp)
}

// round 11
// speedup vs baseline: 2.0385x; 2.0385x over previous
#include <cuda_runtime.h>
#include <cuda_fp16.h>
#include <cstddef>
#include <cstdint>

#define BATCH   64
#define NCAPS   32
#define NROUTES 2048
#define INDIM   16
#define OUTDIM  32
#define NITERS  3
#define NWARPS  16

// Global fp16 prior buffer (static device scratch).
// half2 layout: pri[c][bp][n][b1][oh], oh = o/2 (16 half2 per (n,b1))
__device__ __half2 g_pri[(size_t)NCAPS * 32 * NROUTES * 2 * 16];

// ================= K1: priors GEMM (W in registers, x from SMEM) =================
// Grid 1024 = (c, 64-route block). Thread = (route rl=t>>3, col-group og=t&7).
// W[64 floats] lives in registers for the whole kernel; loop over 64 batches.
#define K1_XROW  20                        // floats per (b,rl) row (16 + 4 pad)
#define K1_XBUF  (8 * 64 * K1_XROW)        // 10240 floats per buffer
#define K1_SMEM_BYTES (2 * K1_XBUF * 4)    // 81920 (double buffered)

__global__ void __launch_bounds__(512)
caps_k1_priors(const float* __restrict__ x, const float* __restrict__ W)
{
    extern __shared__ float xsh[];   // [2][8 b][64 rl][20]
    const int t  = threadIdx.x;
    const int rl = t >> 3;           // 0..63
    const int og = t & 7;            // 0..7
    const int c  = blockIdx.x >> 5;
    const int r0 = (blockIdx.x & 31) * 64;
    const int n  = r0 + rl;

    // W -> registers: wreg[i*4+j] = W[c][n][i][og*4+j]  (coalesced LDG.128)
    float wreg[64];
    {
        const float4* W4 = reinterpret_cast<const float4*>(W)
                         + ((size_t)(c * NROUTES + n) * INDIM) * 8 + og;
#pragma unroll
        for (int i = 0; i < 16; i++) {
            float4 w = __ldg(W4 + i * 8);
            wreg[i * 4 + 0] = w.x; wreg[i * 4 + 1] = w.y;
            wreg[i * 4 + 2] = w.z; wreg[i * 4 + 3] = w.w;
        }
    }

    const float4* x4 = reinterpret_cast<const float4*>(x);

    // prologue: stage batch-group 0 into buffer 0
#pragma unroll
    for (int k = 0; k < 4; k++) {
        int idx = t + k * 512;
        int bl = idx >> 8, rem = idx & 255;
        int rr = rem >> 2, q = rem & 3;
        float4 v = __ldg(x4 + ((size_t)bl * NROUTES + r0 + rr) * 4 + q);
        *reinterpret_cast<float4*>(&xsh[(bl * 64 + rr) * K1_XROW + q * 4]) = v;
    }
    __syncthreads();

    for (int g = 0; g < 8; g++) {
        float* buf  = xsh + (g & 1) * K1_XBUF;
        float* nbuf = xsh + ((g + 1) & 1) * K1_XBUF;

        if (g + 1 < 8) {
#pragma unroll
            for (int k = 0; k < 4; k++) {
                int idx = t + k * 512;
                int bl = idx >> 8, rem = idx & 255;
                int rr = rem >> 2, q = rem & 3;
                float4 v = __ldg(x4 + ((size_t)((g + 1) * 8 + bl) * NROUTES + r0 + rr) * 4 + q);
                *reinterpret_cast<float4*>(&nbuf[(bl * 64 + rr) * K1_XROW + q * 4]) = v;
            }
        }

#pragma unroll
        for (int bl = 0; bl < 8; bl++) {
            const float* xr = &buf[(bl * 64 + rl) * K1_XROW];
            float a0 = 0.f, a1 = 0.f, a2 = 0.f, a3 = 0.f;
#pragma unroll
            for (int q = 0; q < 4; q++) {
                float4 xq = *reinterpret_cast<const float4*>(xr + q * 4);
                const float* wq = wreg + q * 16;
                a0 = fmaf(xq.x, wq[0],  a0); a1 = fmaf(xq.x, wq[1],  a1);
                a2 = fmaf(xq.x, wq[2],  a2); a3 = fmaf(xq.x, wq[3],  a3);
                a0 = fmaf(xq.y, wq[4],  a0); a1 = fmaf(xq.y, wq[5],  a1);
                a2 = fmaf(xq.y, wq[6],  a2); a3 = fmaf(xq.y, wq[7],  a3);
                a0 = fmaf(xq.z, wq[8],  a0); a1 = fmaf(xq.z, wq[9],  a1);
                a2 = fmaf(xq.z, wq[10], a2); a3 = fmaf(xq.z, wq[11], a3);
                a0 = fmaf(xq.w, wq[12], a0); a1 = fmaf(xq.w, wq[13], a1);
                a2 = fmaf(xq.w, wq[14], a2); a3 = fmaf(xq.w, wq[15], a3);
            }
            const int b = g * 8 + bl;
            size_t off = ((((size_t)c * 32 + (b >> 1)) * NROUTES + n) * 2 + (b & 1)) * 16
                       + og * 2;
            union { __half2 h[2]; uint2 u; } pk;
            pk.h[0] = __floats2half2_rn(a0, a1);
            pk.h[1] = __floats2half2_rn(a2, a3);
            *reinterpret_cast<uint2*>(&g_pri[off]) = pk.u;
        }
        __syncthreads();
    }
}

// ================= K2: routing (1 batch per CTA, 2 CTAs/SM) =================
#define SPH 17
#define K2_SP_HALF2S (1024 * SPH)
#define K2_NSCR (32 + 32 + 16 + NWARPS * 32 + 4)
#define K2_SMEM_BYTES ((K2_SP_HALF2S + K2_NSCR) * 4)   // 72016

__global__ void __launch_bounds__(512, 2)
caps_k2_route(float* __restrict__ out)
{
    extern __shared__ __half2 smh[];
    __half2* sp  = smh;
    float* scr  = reinterpret_cast<float*>(smh + K2_SP_HALF2S);
    float* Vsh  = scr;                       // 32
    float* sred = scr + 32;                  // 32
    float* wred = scr + 64;                  // 16
    float* wvec = scr + 80;                  // 16*32
    float* scal = scr + 80 + NWARPS * 32;    // 4

    const int t    = threadIdx.x;
    const int lane = t & 31;
    const int wid  = t >> 5;
    const int b1   = blockIdx.x & 1;
    const int bp   = (blockIdx.x >> 1) & 31;
    const int c    = blockIdx.x >> 6;
    const int b    = bp * 2 + b1;

    const float4* P4 = reinterpret_cast<const float4*>(
        g_pri + (((size_t)c * 32 + bp) * NROUTES) * 32);
    // our batch's route n = 4 float4s at P4[n*8 + b1*4 + q]

    // ---- pass 1: routes 1024..2047 -> sp rows 0..1023 ----
#pragma unroll 2
    for (int k = 0; k < 8; k++) {
        int idx = t + k * 512;
        int nl = idx >> 2, q = idx & 3;
        float4 v = __ldg(P4 + (size_t)(1024 + nl) * 8 + b1 * 4 + q);
        const __half2* h = reinterpret_cast<const __half2*>(&v);
        __half2* dst = sp + (size_t)nl * SPH + q * 4;
        dst[0] = h[0]; dst[1] = h[1]; dst[2] = h[2]; dst[3] = h[3];
    }
    __syncthreads();

    // pull register rows: A = route 1024+t, B = route 1536+t
    __half2 A[16], B[16];
    {
        const __half2* pA = sp + (size_t)t * SPH;
        const __half2* pB = sp + (size_t)(512 + t) * SPH;
#pragma unroll
        for (int j = 0; j < 16; j++) { A[j] = pA[j]; B[j] = pB[j]; }
    }
    __syncthreads();

    // ---- pass 2: routes 0..1023 -> sp rows ----
#pragma unroll 2
    for (int k = 0; k < 8; k++) {
        int idx = t + k * 512;
        int nl = idx >> 2, q = idx & 3;
        float4 v = __ldg(P4 + (size_t)nl * 8 + b1 * 4 + q);
        const __half2* h = reinterpret_cast<const __half2*>(&v);
        __half2* dst = sp + (size_t)nl * SPH + q * 4;
        dst[0] = h[0]; dst[1] = h[1]; dst[2] = h[2]; dst[3] = h[3];
    }
    __syncthreads();

    const __half2* spC = sp + (size_t)t * SPH;          // route t
    const __half2* spD = sp + (size_t)(512 + t) * SPH;  // route 512+t

    if (t < 32) Vsh[t] = 0.f;
    __syncthreads();

    for (int it = 0; it < NITERS; it++) {
        float p0, p1, p2, p3;
        if (it == 0) {
            p0 = p1 = p2 = p3 = 1.0f / (float)NROUTES;
        } else {
            float l0 = 0.f, l1 = 0.f, l2 = 0.f, l3 = 0.f;
#pragma unroll
            for (int j = 0; j < 16; j++) {
                float v0 = Vsh[2 * j], v1 = Vsh[2 * j + 1];
                float2 a  = __half22float2(A[j]);
                float2 bb = __half22float2(B[j]);
                float2 cc = __half22float2(spC[j]);
                float2 dd = __half22float2(spD[j]);
                l0 += a.x  * v0 + a.y  * v1;
                l1 += bb.x * v0 + bb.y * v1;
                l2 += cc.x * v0 + cc.y * v1;
                l3 += dd.x * v0 + dd.y * v1;
            }
            float m = fmaxf(fmaxf(l0, l1), fmaxf(l2, l3));
#pragma unroll
            for (int s = 16; s; s >>= 1) m = fmaxf(m, __shfl_xor_sync(0xffffffffu, m, s));
            if (lane == 0) wred[wid] = m;
            __syncthreads();
            if (wid == 0) {
                float mm = (lane < NWARPS) ? wred[lane] : -3.402823e38f;
#pragma unroll
                for (int s = 16; s; s >>= 1) mm = fmaxf(mm, __shfl_xor_sync(0xffffffffu, mm, s));
                if (lane == 0) scal[0] = mm;
            }
            __syncthreads();
            const float bmax = scal[0];

            float e0 = __expf(l0 - bmax);
            float e1 = __expf(l1 - bmax);
            float e2 = __expf(l2 - bmax);
            float e3 = __expf(l3 - bmax);
            float zs = e0 + e1 + e2 + e3;
#pragma unroll
            for (int s = 16; s; s >>= 1) zs += __shfl_xor_sync(0xffffffffu, zs, s);
            if (lane == 0) wred[wid] = zs;
            __syncthreads();
            if (wid == 0) {
                float zz = (lane < NWARPS) ? wred[lane] : 0.f;
#pragma unroll
                for (int s = 16; s; s >>= 1) zz += __shfl_xor_sync(0xffffffffu, zz, s);
                if (lane == 0) scal[1] = zz;
            }
            __syncthreads();
            const float invZ = 1.0f / scal[1];
            p0 = e0 * invZ; p1 = e1 * invZ; p2 = e2 * invZ; p3 = e3 * invZ;
        }

        // s = sum_n probs_n * p_n ; chunked (4 x 8) tree to cap regs
#pragma unroll
        for (int ch = 0; ch < 4; ch++) {
            float ps[8];
#pragma unroll
            for (int jj = 0; jj < 4; jj++) {
                int j = ch * 4 + jj;
                float2 a  = __half22float2(A[j]);
                float2 bb = __half22float2(B[j]);
                float2 cc = __half22float2(spC[j]);
                float2 dd = __half22float2(spD[j]);
                ps[2 * jj]     = p0 * a.x + p1 * bb.x + p2 * cc.x + p3 * dd.x;
                ps[2 * jj + 1] = p0 * a.y + p1 * bb.y + p2 * cc.y + p3 * dd.y;
            }
#pragma unroll
            for (int s = 16; s; s >>= 1) {
#pragma unroll
                for (int o = 0; o < 8; o++)
                    ps[o] += __shfl_xor_sync(0xffffffffu, ps[o], s);
            }
            if (lane == 0) {
#pragma unroll
                for (int o = 0; o < 8; o++) wvec[wid * 32 + ch * 8 + o] = ps[o];
            }
        }
        __syncthreads();
        if (t < 32) {
            float sv = 0.f;
#pragma unroll
            for (int w = 0; w < NWARPS; w++) sv += wvec[w * 32 + t];
            sred[t] = sv;
        }
        __syncthreads();

        if (t < 32) {
            float nr = 0.f;
#pragma unroll
            for (int o = 0; o < OUTDIM; o++) { float sv = sred[o]; nr += sv * sv; }
            float scale = (nr / (1.0f + nr)) * rsqrtf(nr);
            float v = scale * sred[t];
            Vsh[t] += v;
            if (it == NITERS - 1)
                out[((size_t)b * NCAPS + c) * OUTDIM + t] = v;
        }
        __syncthreads();
    }
}

extern "C" void kernel_launch(void* const* d_in, const int* in_sizes, int n_in,
                              void* d_out, int out_size)
{
    const float* x = (const float*)d_in[0];         // [64, 2048, 16]
    const float* W = (const float*)d_in[1];         // [32, 2048, 16, 32]
    float* out = (float*)d_out;                     // [64, 32, 32]

    cudaFuncSetAttribute(caps_k1_priors,
                         cudaFuncAttributeMaxDynamicSharedMemorySize, K1_SMEM_BYTES);
    cudaFuncSetAttribute(caps_k2_route,
                         cudaFuncAttributeMaxDynamicSharedMemorySize, K2_SMEM_BYTES);

    caps_k1_priors<<<NCAPS * 32, 512, K1_SMEM_BYTES>>>(x, W);   // (c, 64-route block)
    caps_k2_route<<<NCAPS * BATCH, 512, K2_SMEM_BYTES>>>(out);  // (c, bp, b1)
}

// round 12
// speedup vs baseline: 2.3116x; 1.1340x over previous
#include <cuda_runtime.h>
#include <cuda_fp16.h>
#include <cstddef>
#include <cstdint>

#define BATCH   64
#define NCAPS   32
#define NROUTES 2048
#define INDIM   16
#define OUTDIM  32
#define NITERS  3
#define NWARPS  16

typedef unsigned long long u64;
#define FMA2(d, a, b, c) \
    asm("fma.rn.f32x2 %0, %1, %2, %3;" : "=l"(d) : "l"(a), "l"(b), "l"(c))
#define PACKF2(o, lo, hi) \
    asm("mov.b64 %0, {%1, %2};" : "=l"(o) : "f"(lo), "f"(hi))
#define UNPACKF2(lo, hi, in) \
    asm("mov.b64 {%0, %1}, %2;" : "=f"(lo), "=f"(hi) : "l"(in))

// Global fp16 prior buffer (static device scratch).
// half2 layout: pri[c][bp][n][b1][oh], oh = o/2 (16 half2 per (n,b1))
__device__ __half2 g_pri[(size_t)NCAPS * 32 * NROUTES * 2 * 16];

// ================= K1: priors GEMM (W packed in registers, f32x2 FMA) =================
// Grid 1024 = (c, 64-route block). Thread = (route rl=t>>3, col-group og=t&7).
#define K1_XROW  20                        // floats per (b,rl) row (16 + 4 pad)
#define K1_XBUF  (8 * 64 * K1_XROW)        // 10240 floats per buffer
#define K1_SMEM_BYTES (2 * K1_XBUF * 4)    // 81920 (double buffered)

__global__ void __launch_bounds__(512)
caps_k1_priors(const float* __restrict__ x, const float* __restrict__ W)
{
    extern __shared__ float xsh[];   // [2][8 b][64 rl][20]
    const int t  = threadIdx.x;
    const int rl = t >> 3;           // 0..63
    const int og = t & 7;            // 0..7
    const int c  = blockIdx.x >> 5;
    const int r0 = (blockIdx.x & 31) * 64;
    const int n  = r0 + rl;

    // W -> packed register pairs: wp[i*2]   = {W[i][og*4+0], W[i][og*4+1]}
    //                             wp[i*2+1] = {W[i][og*4+2], W[i][og*4+3]}
    u64 wp[32];
    {
        const float4* W4 = reinterpret_cast<const float4*>(W)
                         + ((size_t)(c * NROUTES + n) * INDIM) * 8 + og;
#pragma unroll
        for (int i = 0; i < 16; i++) {
            float4 w = __ldg(W4 + i * 8);
            PACKF2(wp[i * 2],     w.x, w.y);
            PACKF2(wp[i * 2 + 1], w.z, w.w);
        }
    }

    const float4* x4 = reinterpret_cast<const float4*>(x);

    // prologue: stage batch-group 0 into buffer 0
#pragma unroll
    for (int k = 0; k < 4; k++) {
        int idx = t + k * 512;
        int bl = idx >> 8, rem = idx & 255;
        int rr = rem >> 2, q = rem & 3;
        float4 v = __ldg(x4 + ((size_t)bl * NROUTES + r0 + rr) * 4 + q);
        *reinterpret_cast<float4*>(&xsh[(bl * 64 + rr) * K1_XROW + q * 4]) = v;
    }
    __syncthreads();

    for (int g = 0; g < 8; g++) {
        float* buf  = xsh + (g & 1) * K1_XBUF;
        float* nbuf = xsh + ((g + 1) & 1) * K1_XBUF;

        if (g + 1 < 8) {
#pragma unroll
            for (int k = 0; k < 4; k++) {
                int idx = t + k * 512;
                int bl = idx >> 8, rem = idx & 255;
                int rr = rem >> 2, q = rem & 3;
                float4 v = __ldg(x4 + ((size_t)((g + 1) * 8 + bl) * NROUTES + r0 + rr) * 4 + q);
                *reinterpret_cast<float4*>(&nbuf[(bl * 64 + rr) * K1_XROW + q * 4]) = v;
            }
        }

#pragma unroll
        for (int bl = 0; bl < 8; bl++) {
            const float* xr = &buf[(bl * 64 + rl) * K1_XROW];
            u64 a01 = 0ull, a23 = 0ull;   // {+0.f,+0.f} bit pattern
#pragma unroll
            for (int q = 0; q < 4; q++) {
                float4 xq = *reinterpret_cast<const float4*>(xr + q * 4);
                u64 xx;
                PACKF2(xx, xq.x, xq.x);
                FMA2(a01, xx, wp[(q * 4 + 0) * 2],     a01);
                FMA2(a23, xx, wp[(q * 4 + 0) * 2 + 1], a23);
                PACKF2(xx, xq.y, xq.y);
                FMA2(a01, xx, wp[(q * 4 + 1) * 2],     a01);
                FMA2(a23, xx, wp[(q * 4 + 1) * 2 + 1], a23);
                PACKF2(xx, xq.z, xq.z);
                FMA2(a01, xx, wp[(q * 4 + 2) * 2],     a01);
                FMA2(a23, xx, wp[(q * 4 + 2) * 2 + 1], a23);
                PACKF2(xx, xq.w, xq.w);
                FMA2(a01, xx, wp[(q * 4 + 3) * 2],     a01);
                FMA2(a23, xx, wp[(q * 4 + 3) * 2 + 1], a23);
            }
            float a0, a1, a2, a3;
            UNPACKF2(a0, a1, a01);
            UNPACKF2(a2, a3, a23);

            const int b = g * 8 + bl;
            size_t off = ((((size_t)c * 32 + (b >> 1)) * NROUTES + n) * 2 + (b & 1)) * 16
                       + og * 2;
            union { __half2 h[2]; uint2 u; } pk;
            pk.h[0] = __floats2half2_rn(a0, a1);
            pk.h[1] = __floats2half2_rn(a2, a3);
            *reinterpret_cast<uint2*>(&g_pri[off]) = pk.u;
        }
        __syncthreads();
    }
}

// ================= K2: routing (1 batch per CTA, 2 CTAs/SM) =================
#define SPH 17
#define K2_SP_HALF2S (1024 * SPH)
#define K2_NSCR (32 + 32 + 16 + NWARPS * 32 + 4)
#define K2_SMEM_BYTES ((K2_SP_HALF2S + K2_NSCR) * 4)   // 72016

__global__ void __launch_bounds__(512, 2)
caps_k2_route(float* __restrict__ out)
{
    extern __shared__ __half2 smh[];
    __half2* sp  = smh;
    float* scr  = reinterpret_cast<float*>(smh + K2_SP_HALF2S);
    float* Vsh  = scr;                       // 32
    float* sred = scr + 32;                  // 32
    float* wred = scr + 64;                  // 16
    float* wvec = scr + 80;                  // 16*32
    float* scal = scr + 80 + NWARPS * 32;    // 4

    const int t    = threadIdx.x;
    const int lane = t & 31;
    const int wid  = t >> 5;
    const int b1   = blockIdx.x & 1;
    const int bp   = (blockIdx.x >> 1) & 31;
    const int c    = blockIdx.x >> 6;
    const int b    = bp * 2 + b1;

    const float4* P4 = reinterpret_cast<const float4*>(
        g_pri + (((size_t)c * 32 + bp) * NROUTES) * 32);

    // ---- pass 1: routes 1024..2047 -> sp rows 0..1023 ----
#pragma unroll 2
    for (int k = 0; k < 8; k++) {
        int idx = t + k * 512;
        int nl = idx >> 2, q = idx & 3;
        float4 v = __ldg(P4 + (size_t)(1024 + nl) * 8 + b1 * 4 + q);
        const __half2* h = reinterpret_cast<const __half2*>(&v);
        __half2* dst = sp + (size_t)nl * SPH + q * 4;
        dst[0] = h[0]; dst[1] = h[1]; dst[2] = h[2]; dst[3] = h[3];
    }
    __syncthreads();

    __half2 A[16], B[16];
    {
        const __half2* pA = sp + (size_t)t * SPH;
        const __half2* pB = sp + (size_t)(512 + t) * SPH;
#pragma unroll
        for (int j = 0; j < 16; j++) { A[j] = pA[j]; B[j] = pB[j]; }
    }
    __syncthreads();

    // ---- pass 2: routes 0..1023 -> sp rows ----
#pragma unroll 2
    for (int k = 0; k < 8; k++) {
        int idx = t + k * 512;
        int nl = idx >> 2, q = idx & 3;
        float4 v = __ldg(P4 + (size_t)nl * 8 + b1 * 4 + q);
        const __half2* h = reinterpret_cast<const __half2*>(&v);
        __half2* dst = sp + (size_t)nl * SPH + q * 4;
        dst[0] = h[0]; dst[1] = h[1]; dst[2] = h[2]; dst[3] = h[3];
    }
    __syncthreads();

    const __half2* spC = sp + (size_t)t * SPH;          // route t
    const __half2* spD = sp + (size_t)(512 + t) * SPH;  // route 512+t

    if (t < 32) Vsh[t] = 0.f;
    __syncthreads();

    for (int it = 0; it < NITERS; it++) {
        float p0, p1, p2, p3;
        if (it == 0) {
            p0 = p1 = p2 = p3 = 1.0f / (float)NROUTES;
        } else {
            float l0 = 0.f, l1 = 0.f, l2 = 0.f, l3 = 0.f;
#pragma unroll
            for (int j = 0; j < 16; j++) {
                float v0 = Vsh[2 * j], v1 = Vsh[2 * j + 1];
                float2 a  = __half22float2(A[j]);
                float2 bb = __half22float2(B[j]);
                float2 cc = __half22float2(spC[j]);
                float2 dd = __half22float2(spD[j]);
                l0 += a.x  * v0 + a.y  * v1;
                l1 += bb.x * v0 + bb.y * v1;
                l2 += cc.x * v0 + cc.y * v1;
                l3 += dd.x * v0 + dd.y * v1;
            }
            float m = fmaxf(fmaxf(l0, l1), fmaxf(l2, l3));
#pragma unroll
            for (int s = 16; s; s >>= 1) m = fmaxf(m, __shfl_xor_sync(0xffffffffu, m, s));
            if (lane == 0) wred[wid] = m;
            __syncthreads();
            if (wid == 0) {
                float mm = (lane < NWARPS) ? wred[lane] : -3.402823e38f;
#pragma unroll
                for (int s = 16; s; s >>= 1) mm = fmaxf(mm, __shfl_xor_sync(0xffffffffu, mm, s));
                if (lane == 0) scal[0] = mm;
            }
            __syncthreads();
            const float bmax = scal[0];

            float e0 = __expf(l0 - bmax);
            float e1 = __expf(l1 - bmax);
            float e2 = __expf(l2 - bmax);
            float e3 = __expf(l3 - bmax);
            float zs = e0 + e1 + e2 + e3;
#pragma unroll
            for (int s = 16; s; s >>= 1) zs += __shfl_xor_sync(0xffffffffu, zs, s);
            if (lane == 0) wred[wid] = zs;
            __syncthreads();
            if (wid == 0) {
                float zz = (lane < NWARPS) ? wred[lane] : 0.f;
#pragma unroll
                for (int s = 16; s; s >>= 1) zz += __shfl_xor_sync(0xffffffffu, zz, s);
                if (lane == 0) scal[1] = zz;
            }
            __syncthreads();
            const float invZ = 1.0f / scal[1];
            p0 = e0 * invZ; p1 = e1 * invZ; p2 = e2 * invZ; p3 = e3 * invZ;
        }

        // s = sum_n probs_n * p_n : multi-value exchange reduction per 8-chunk.
        // After masks {16,8,4} each lane holds the sum (over lanes ≡ lane mod 4)
        // for output j=(lane>>2)&7; masks {2,1} finish; lanes with lane&3==0 store.
#pragma unroll
        for (int ch = 0; ch < 4; ch++) {
            float v[8];
#pragma unroll
            for (int jj = 0; jj < 4; jj++) {
                int j = ch * 4 + jj;
                float2 a  = __half22float2(A[j]);
                float2 bb = __half22float2(B[j]);
                float2 cc = __half22float2(spC[j]);
                float2 dd = __half22float2(spD[j]);
                v[2 * jj]     = p0 * a.x + p1 * bb.x + p2 * cc.x + p3 * dd.x;
                v[2 * jj + 1] = p0 * a.y + p1 * bb.y + p2 * cc.y + p3 * dd.y;
            }
            {
                bool up = (lane & 16) != 0;
#pragma unroll
                for (int i = 0; i < 4; i++) {
                    float keep = up ? v[i + 4] : v[i];
                    float send = up ? v[i] : v[i + 4];
                    v[i] = keep + __shfl_xor_sync(0xffffffffu, send, 16);
                }
                up = (lane & 8) != 0;
#pragma unroll
                for (int i = 0; i < 2; i++) {
                    float keep = up ? v[i + 2] : v[i];
                    float send = up ? v[i] : v[i + 2];
                    v[i] = keep + __shfl_xor_sync(0xffffffffu, send, 8);
                }
                up = (lane & 4) != 0;
                {
                    float keep = up ? v[1] : v[0];
                    float send = up ? v[0] : v[1];
                    v[0] = keep + __shfl_xor_sync(0xffffffffu, send, 4);
                }
                v[0] += __shfl_xor_sync(0xffffffffu, v[0], 2);
                v[0] += __shfl_xor_sync(0xffffffffu, v[0], 1);
            }
            if ((lane & 3) == 0)
                wvec[wid * 32 + ch * 8 + (lane >> 2)] = v[0];
        }
        __syncthreads();
        if (t < 32) {
            float sv = 0.f;
#pragma unroll
            for (int w = 0; w < NWARPS; w++) sv += wvec[w * 32 + t];
            sred[t] = sv;
        }
        __syncthreads();

        if (t < 32) {
            float nr = 0.f;
#pragma unroll
            for (int o = 0; o < OUTDIM; o++) { float sv = sred[o]; nr += sv * sv; }
            float scale = (nr / (1.0f + nr)) * rsqrtf(nr);
            float v = scale * sred[t];
            Vsh[t] += v;
            if (it == NITERS - 1)
                out[((size_t)b * NCAPS + c) * OUTDIM + t] = v;
        }
        __syncthreads();
    }
}

extern "C" void kernel_launch(void* const* d_in, const int* in_sizes, int n_in,
                              void* d_out, int out_size)
{
    const float* x = (const float*)d_in[0];         // [64, 2048, 16]
    const float* W = (const float*)d_in[1];         // [32, 2048, 16, 32]
    float* out = (float*)d_out;                     // [64, 32, 32]

    cudaFuncSetAttribute(caps_k1_priors,
                         cudaFuncAttributeMaxDynamicSharedMemorySize, K1_SMEM_BYTES);
    cudaFuncSetAttribute(caps_k2_route,
                         cudaFuncAttributeMaxDynamicSharedMemorySize, K2_SMEM_BYTES);

    caps_k1_priors<<<NCAPS * 32, 512, K1_SMEM_BYTES>>>(x, W);   // (c, 64-route block)
    caps_k2_route<<<NCAPS * BATCH, 512, K2_SMEM_BYTES>>>(out);  // (c, bp, b1)
}